// round 3
// baseline (speedup 1.0000x reference)
#include <cuda_runtime.h>
#include <cuda_bf16.h>
#include <cstdint>
#include <cstddef>

#define B_   64
#define S_   512
#define E_   300
#define EP_  304
#define H_   256
#define M_   32768

__device__ float g_x[M_ * EP_];            // [S,B,EP], row m=s*64+b
__device__ float g_w0pad[2][1024 * EP_];   // padded w_ih_l0{f,b}
__device__ float g_gx0[M_ * 2048];         // layer0 gate inputs [m, dir*1024+g]
__device__ float g_h1 [M_ * 512];          // layer0 out [m, dir*256+j]
__device__ float g_gx1[M_ * 2048];
__device__ float g_h2 [M_ * 512];
__device__ float g_hbuf[2][2][B_ * H_];    // ping-pong h per dir
__device__ float g_err[M_];
__device__ unsigned g_cnt;

__device__ __forceinline__ float sigm(float x) { return 1.0f / (1.0f + expf(-x)); }

__device__ __forceinline__ void gbar(unsigned* ph, unsigned nct) {
    __syncthreads();
    if (threadIdx.x == 0) {
        __threadfence();
        atomicAdd(&g_cnt, 1u);
        const unsigned target = (*ph + 1u) * nct;
        while (*(volatile unsigned*)&g_cnt < target) __nanosleep(64);
        __threadfence();
    }
    ++(*ph);
    __syncthreads();
}

__global__ void reset_kernel() { g_cnt = 0u; }

__global__ void gather_kernel(const int* __restrict__ ids, const float* __restrict__ emb) {
    int m = blockIdx.x, s = m >> 6, b = m & 63;
    int id = ids[b * S_ + s];
    const float* src = emb + (size_t)id * E_;
    float* dst = g_x + (size_t)m * EP_;
    for (int e = threadIdx.x; e < EP_; e += blockDim.x)
        dst[e] = (e < E_) ? src[e] : 0.0f;
}

__global__ void padw_kernel(const float* __restrict__ wf, const float* __restrict__ wb) {
    int row = blockIdx.x & 1023, dir = blockIdx.x >> 10;
    const float* src = (dir ? wb : wf) + (size_t)row * E_;
    float* dst = g_w0pad[dir] + (size_t)row * EP_;
    for (int e = threadIdx.x; e < EP_; e += blockDim.x)
        dst[e] = (e < E_) ? src[e] : 0.0f;
}

// C[m, dir*1024+n] = b1[n]+b2[n] + sum_k A[m,k]*W[n,k]; BM=128,BN=64,BK=16
__global__ void sgemm_kernel(int layer, int dir,
                             const float* __restrict__ Wext,
                             const float* __restrict__ b1,
                             const float* __restrict__ b2) {
    const float* A; const float* W; float* C; int lda, K;
    if (layer == 0) { A = g_x;  lda = EP_; K = EP_; W = g_w0pad[dir]; C = g_gx0; }
    else            { A = g_h1; lda = 512; K = 512; W = Wext;         C = g_gx1; }
    const int coloff = dir << 10;

    __shared__ float As[16][132];
    __shared__ float Bs[16][68];

    const int tid = threadIdx.x;
    const int m0 = blockIdx.y * 128, n0 = blockIdx.x * 64;
    const int tx = tid & 15, ty = tid >> 4;
    const int arow = tid >> 2, acol = (tid & 3) * 4;

    float acc[8][4];
#pragma unroll
    for (int i = 0; i < 8; ++i)
#pragma unroll
        for (int j = 0; j < 4; ++j) acc[i][j] = 0.0f;

    for (int k0 = 0; k0 < K; k0 += 16) {
        float4 a0 = *(const float4*)(A + (size_t)(m0 + arow)      * lda + k0 + acol);
        float4 a1 = *(const float4*)(A + (size_t)(m0 + arow + 64) * lda + k0 + acol);
        float4 bv = *(const float4*)(W + (size_t)(n0 + arow)      * lda + k0 + acol);
        __syncthreads();
        As[acol + 0][arow] = a0.x; As[acol + 1][arow] = a0.y;
        As[acol + 2][arow] = a0.z; As[acol + 3][arow] = a0.w;
        As[acol + 0][arow + 64] = a1.x; As[acol + 1][arow + 64] = a1.y;
        As[acol + 2][arow + 64] = a1.z; As[acol + 3][arow + 64] = a1.w;
        Bs[acol + 0][arow] = bv.x; Bs[acol + 1][arow] = bv.y;
        Bs[acol + 2][arow] = bv.z; Bs[acol + 3][arow] = bv.w;
        __syncthreads();
#pragma unroll
        for (int k = 0; k < 16; ++k) {
            float av[8], bw[4];
#pragma unroll
            for (int i = 0; i < 8; ++i) av[i] = As[k][ty * 8 + i];
#pragma unroll
            for (int j = 0; j < 4; ++j) bw[j] = Bs[k][tx * 4 + j];
#pragma unroll
            for (int i = 0; i < 8; ++i)
#pragma unroll
                for (int j = 0; j < 4; ++j)
                    acc[i][j] = fmaf(av[i], bw[j], acc[i][j]);
        }
    }
    const int ng = n0 + tx * 4;
    float bsum[4];
#pragma unroll
    for (int j = 0; j < 4; ++j) bsum[j] = b1[ng + j] + b2[ng + j];
#pragma unroll
    for (int i = 0; i < 8; ++i) {
        int m = m0 + ty * 8 + i;
        float4 o;
        o.x = acc[i][0] + bsum[0]; o.y = acc[i][1] + bsum[1];
        o.z = acc[i][2] + bsum[2]; o.w = acc[i][3] + bsum[3];
        *(float4*)(C + (size_t)m * 2048 + coloff + ng) = o;
    }
}

// Persistent bi-LSTM layer: 128 CTAs (64/dir), 256 thr; CTA owns 4 h-dims.
#define LSTM_SMEM_FLOATS (4128 + 16384 + 1024 + 1040 + 256)

__global__ void lstm_kernel(int layer,
                            const float* __restrict__ whh_f,
                            const float* __restrict__ whh_b) {
    extern __shared__ float smf[];
    float* Wsl = smf;            // [16][258]
    float* Hs  = smf + 4128;     // [64][256]
    float* Gx  = Hs + 16384;     // [16][64]
    float* Gs  = Gx + 1024;      // [16][65]
    float* Cs  = Gs + 1040;      // [64][4]

    const float* gx   = layer ? g_gx1 : g_gx0;
    float*       hout = layer ? g_h2  : g_h1;

    const int tid = threadIdx.x;
    const int dir = blockIdx.x >> 6;
    const int j0  = (blockIdx.x & 63) * 4;
    const unsigned nct = gridDim.x;
    const float* whh = dir ? whh_b : whh_f;

    {   // weight slice: row r=grp*4+jj -> w_hh[grp*256 + j0+jj][:]
        int r = tid >> 4, k0 = (tid & 15) * 16;
        int grp = r >> 2, jj = r & 3;
        const float* src = whh + (size_t)((grp << 8) + j0 + jj) * 256 + k0;
        float* dst = Wsl + r * 258 + k0;
#pragma unroll
        for (int i = 0; i < 16; ++i) dst[i] = src[i];
    }
    {   // zero c and initial h
        int b = tid >> 2, jj = tid & 3;
        Cs[(b << 2) + jj] = 0.0f;
        g_hbuf[0][dir][(b << 8) + j0 + jj] = 0.0f;
    }
    unsigned ph = 0;
    gbar(&ph, nct);

    const int kid  = tid & 7;
    const int tile = tid >> 3;
    const int r0 = (tile & 3) * 4;
    const int b0 = (tile >> 2) * 8;

    for (int t = 0; t < 512; ++t) {
        const int s = dir ? (511 - t) : t;

        const float4* hold = (const float4*)g_hbuf[t & 1][dir];
        float4* hsv = (float4*)Hs;
#pragma unroll
        for (int i = 0; i < 16; ++i)
            hsv[(i << 8) + tid] = __ldcg(hold + (i << 8) + tid);

        {
            int b = tid >> 2, grp = tid & 3;
            const float* gp = gx + ((size_t)((s << 6) + b) << 11) + (dir << 10) + (grp << 8) + j0;
            float4 v = *(const float4*)gp;
            float* gxd = Gx + ((grp << 2) << 6) + b;
            gxd[0] = v.x; gxd[64] = v.y; gxd[128] = v.z; gxd[192] = v.w;
        }
        __syncthreads();

        float acc[4][8];
#pragma unroll
        for (int i = 0; i < 4; ++i)
#pragma unroll
            for (int j = 0; j < 8; ++j) acc[i][j] = 0.0f;

        const float* wb = Wsl + r0 * 258 + kid;
        const float* hb = Hs + (b0 << 8) + kid;
#pragma unroll 4
        for (int kk = 0; kk < 32; ++kk) {
            const int k8 = kk << 3;
            float w0 = wb[k8], w1 = wb[258 + k8], w2 = wb[516 + k8], w3 = wb[774 + k8];
#pragma unroll
            for (int j = 0; j < 8; ++j) {
                float hv = hb[(j << 8) + k8];
                acc[0][j] = fmaf(w0, hv, acc[0][j]);
                acc[1][j] = fmaf(w1, hv, acc[1][j]);
                acc[2][j] = fmaf(w2, hv, acc[2][j]);
                acc[3][j] = fmaf(w3, hv, acc[3][j]);
            }
        }
#pragma unroll
        for (int i = 0; i < 4; ++i)
#pragma unroll
            for (int j = 0; j < 8; ++j) {
                float v = acc[i][j];
                v += __shfl_xor_sync(0xffffffffu, v, 1);
                v += __shfl_xor_sync(0xffffffffu, v, 2);
                v += __shfl_xor_sync(0xffffffffu, v, 4);
                if (kid == 0)
                    Gs[(r0 + i) * 65 + b0 + j] = v + Gx[((r0 + i) << 6) + b0 + j];
            }
        __syncthreads();

        {
            int b = tid >> 2, jj = tid & 3;
            float gi = Gs[jj * 65 + b];
            float gf = Gs[(4 + jj) * 65 + b];
            float gg = Gs[(8 + jj) * 65 + b];
            float go = Gs[(12 + jj) * 65 + b];
            float c = sigm(gf) * Cs[(b << 2) + jj] + sigm(gi) * tanhf(gg);
            Cs[(b << 2) + jj] = c;
            float h = sigm(go) * tanhf(c);
            g_hbuf[(t + 1) & 1][dir][(b << 8) + j0 + jj] = h;
            hout[((size_t)((s << 6) + b) << 9) + (dir << 8) + j0 + jj] = h;
        }
        gbar(&ph, nct);
    }
}

__global__ void score_kernel(const float* __restrict__ wlin,
                             const float* __restrict__ blin,
                             const float* __restrict__ labels,
                             const int* __restrict__ masks,
                             float* __restrict__ outs) {
    int w = blockIdx.x * 8 + (threadIdx.x >> 5);
    int lane = threadIdx.x & 31;
    int s = w >> 6, b = w & 63;
    const float* hp = g_h2 + (size_t)w * 512;
    float acc = 0.0f;
#pragma unroll
    for (int j = lane; j < 256; j += 32)
        acc += 0.5f * (hp[j] + hp[256 + j]) * wlin[j];
#pragma unroll
    for (int d = 16; d; d >>= 1) acc += __shfl_xor_sync(0xffffffffu, acc, d);
    if (lane == 0) {
        float sc = sigm(acc + blin[0]);
        int oi = b * S_ + s;
        outs[oi] = sc;
        float df = sc - labels[oi];
        g_err[oi] = df * df * (float)masks[oi];
    }
}

__global__ void loss_kernel(const int* __restrict__ masks,
                            float* __restrict__ out, int out_size) {
    __shared__ float sr[64];
    int b = threadIdx.x;
    if (b < 64) {
        float se = 0.0f, sm = 0.0f;
        for (int s = 0; s < S_; ++s) {
            se += g_err[b * S_ + s];
            sm += (float)masks[b * S_ + s];
        }
        sr[b] = se / sm;
    }
    __syncthreads();
    if (threadIdx.x == 0 && out_size > M_) {
        float t = 0.0f;
        for (int i = 0; i < 64; ++i) t += sr[i];
        out[M_] = t / 64.0f;
    }
}

extern "C" void kernel_launch(void* const* d_in, const int* in_sizes, int n_in,
                              void* d_out, int out_size) {
    const int*   ids    = (const int*)d_in[0];
    const float* labels = (const float*)d_in[1];
    const int*   masks  = (const int*)d_in[2];
    const float* emb    = (const float*)d_in[3];
    const float* wih0f = (const float*)d_in[4];
    const float* whh0f = (const float*)d_in[5];
    const float* bih0f = (const float*)d_in[6];
    const float* bhh0f = (const float*)d_in[7];
    const float* wih0b = (const float*)d_in[8];
    const float* whh0b = (const float*)d_in[9];
    const float* bih0b = (const float*)d_in[10];
    const float* bhh0b = (const float*)d_in[11];
    const float* wih1f = (const float*)d_in[12];
    const float* whh1f = (const float*)d_in[13];
    const float* bih1f = (const float*)d_in[14];
    const float* bhh1f = (const float*)d_in[15];
    const float* wih1b = (const float*)d_in[16];
    const float* whh1b = (const float*)d_in[17];
    const float* bih1b = (const float*)d_in[18];
    const float* bhh1b = (const float*)d_in[19];
    const float* wlin  = (const float*)d_in[20];
    const float* blin  = (const float*)d_in[21];
    float* out = (float*)d_out;

    static bool attr_done = false;
    if (!attr_done) {
        cudaFuncSetAttribute(lstm_kernel, cudaFuncAttributeMaxDynamicSharedMemorySize,
                             LSTM_SMEM_FLOATS * 4);
        attr_done = true;
    }

    gather_kernel<<<M_, 128>>>(ids, emb);
    padw_kernel<<<2048, 128>>>(wih0f, wih0b);

    dim3 gg(16, 256);
    sgemm_kernel<<<gg, 256>>>(0, 0, nullptr, bih0f, bhh0f);
    sgemm_kernel<<<gg, 256>>>(0, 1, nullptr, bih0b, bhh0b);

    reset_kernel<<<1, 1>>>();
    lstm_kernel<<<128, 256, LSTM_SMEM_FLOATS * 4>>>(0, whh0f, whh0b);

    sgemm_kernel<<<gg, 256>>>(1, 0, wih1f, bih1f, bhh1f);
    sgemm_kernel<<<gg, 256>>>(1, 1, wih1b, bih1b, bhh1b);

    reset_kernel<<<1, 1>>>();
    lstm_kernel<<<128, 256, LSTM_SMEM_FLOATS * 4>>>(1, whh1f, whh1b);

    score_kernel<<<M_ / 8, 256>>>(wlin, blin, labels, masks, out);
    loss_kernel<<<1, 64>>>(masks, out, out_size);
}

// round 4
// speedup vs baseline: 1.0053x; 1.0053x over previous
#include <cuda_runtime.h>
#include <cuda_bf16.h>
#include <cstdint>
#include <cstddef>

#define B_   64
#define S_   512
#define E_   300
#define EP_  304
#define H_   256
#define M_   32768

__device__ float g_x[M_ * EP_];            // [S,B,EP], row m=s*64+b
__device__ float g_w0pad[2][1024 * EP_];   // padded w_ih_l0{f,b}
__device__ float g_gx0[M_ * 2048];         // layer0 gate inputs [m, dir*1024+g]
__device__ float g_h1 [M_ * 512];          // layer0 out [m, dir*256+j]
__device__ float g_gx1[M_ * 2048];
__device__ float g_h2 [M_ * 512];
__device__ float g_hbuf[2][2][B_ * H_];    // ping-pong h per dir
__device__ float g_err[M_];
__device__ unsigned g_cnt;

__device__ __forceinline__ float sigm(float x) { return 1.0f / (1.0f + expf(-x)); }

__device__ __forceinline__ void gbar(unsigned* ph, unsigned nct) {
    __syncthreads();
    if (threadIdx.x == 0) {
        __threadfence();
        atomicAdd(&g_cnt, 1u);
        const unsigned target = (*ph + 1u) * nct;
        while (*(volatile unsigned*)&g_cnt < target) { }
        __threadfence();
    }
    ++(*ph);
    __syncthreads();
}

__global__ void reset_kernel() { g_cnt = 0u; }

__global__ void gather_kernel(const int* __restrict__ ids, const float* __restrict__ emb) {
    int m = blockIdx.x, s = m >> 6, b = m & 63;
    int id = ids[b * S_ + s];
    const float* src = emb + (size_t)id * E_;
    float* dst = g_x + (size_t)m * EP_;
    for (int e = threadIdx.x; e < EP_; e += blockDim.x)
        dst[e] = (e < E_) ? src[e] : 0.0f;
}

__global__ void padw_kernel(const float* __restrict__ wf, const float* __restrict__ wb) {
    int row = blockIdx.x & 1023, dir = blockIdx.x >> 10;
    const float* src = (dir ? wb : wf) + (size_t)row * E_;
    float* dst = g_w0pad[dir] + (size_t)row * EP_;
    for (int e = threadIdx.x; e < EP_; e += blockDim.x)
        dst[e] = (e < E_) ? src[e] : 0.0f;
}

// C[m, dir*1024+n] = b1[n]+b2[n] + sum_k A[m,k]*W[n,k]
// BM=128,BN=64,BK=16, double-buffered smem, 1 sync/iter.
__global__ void sgemm_kernel(int layer, int dir,
                             const float* __restrict__ Wext,
                             const float* __restrict__ b1,
                             const float* __restrict__ b2) {
    const float* A; const float* W; float* C; int lda, K;
    if (layer == 0) { A = g_x;  lda = EP_; K = EP_; W = g_w0pad[dir]; C = g_gx0; }
    else            { A = g_h1; lda = 512; K = 512; W = Wext;         C = g_gx1; }
    const int coloff = dir << 10;

    __shared__ float As[2][16][132];
    __shared__ float Bs[2][16][68];

    const int tid = threadIdx.x;
    const int m0 = blockIdx.y * 128, n0 = blockIdx.x * 64;
    const int tx = tid & 15, ty = tid >> 4;
    const int arow = tid >> 2, acol = (tid & 3) * 4;

    float acc[8][4];
#pragma unroll
    for (int i = 0; i < 8; ++i)
#pragma unroll
        for (int j = 0; j < 4; ++j) acc[i][j] = 0.0f;

    const int nIter = K >> 4;

    // prologue: load tile 0 into buffer 0
    {
        float4 a0 = *(const float4*)(A + (size_t)(m0 + arow)      * lda + acol);
        float4 a1 = *(const float4*)(A + (size_t)(m0 + arow + 64) * lda + acol);
        float4 bv = *(const float4*)(W + (size_t)(n0 + arow)      * lda + acol);
        As[0][acol + 0][arow] = a0.x; As[0][acol + 1][arow] = a0.y;
        As[0][acol + 2][arow] = a0.z; As[0][acol + 3][arow] = a0.w;
        As[0][acol + 0][arow + 64] = a1.x; As[0][acol + 1][arow + 64] = a1.y;
        As[0][acol + 2][arow + 64] = a1.z; As[0][acol + 3][arow + 64] = a1.w;
        Bs[0][acol + 0][arow] = bv.x; Bs[0][acol + 1][arow] = bv.y;
        Bs[0][acol + 2][arow] = bv.z; Bs[0][acol + 3][arow] = bv.w;
    }
    __syncthreads();

    for (int it = 0; it < nIter; ++it) {
        const int cur = it & 1, nxt = cur ^ 1;
        const bool more = (it + 1 < nIter);
        float4 na0, na1, nbv;
        if (more) {
            const int k0 = (it + 1) << 4;
            na0 = *(const float4*)(A + (size_t)(m0 + arow)      * lda + k0 + acol);
            na1 = *(const float4*)(A + (size_t)(m0 + arow + 64) * lda + k0 + acol);
            nbv = *(const float4*)(W + (size_t)(n0 + arow)      * lda + k0 + acol);
        }
#pragma unroll
        for (int k = 0; k < 16; ++k) {
            float av[8], bw[4];
#pragma unroll
            for (int i = 0; i < 8; ++i) av[i] = As[cur][k][ty * 8 + i];
#pragma unroll
            for (int j = 0; j < 4; ++j) bw[j] = Bs[cur][k][tx * 4 + j];
#pragma unroll
            for (int i = 0; i < 8; ++i)
#pragma unroll
                for (int j = 0; j < 4; ++j)
                    acc[i][j] = fmaf(av[i], bw[j], acc[i][j]);
        }
        if (more) {
            As[nxt][acol + 0][arow] = na0.x; As[nxt][acol + 1][arow] = na0.y;
            As[nxt][acol + 2][arow] = na0.z; As[nxt][acol + 3][arow] = na0.w;
            As[nxt][acol + 0][arow + 64] = na1.x; As[nxt][acol + 1][arow + 64] = na1.y;
            As[nxt][acol + 2][arow + 64] = na1.z; As[nxt][acol + 3][arow + 64] = na1.w;
            Bs[nxt][acol + 0][arow] = nbv.x; Bs[nxt][acol + 1][arow] = nbv.y;
            Bs[nxt][acol + 2][arow] = nbv.z; Bs[nxt][acol + 3][arow] = nbv.w;
        }
        __syncthreads();
    }

    const int ng = n0 + tx * 4;
    float bsum[4];
#pragma unroll
    for (int j = 0; j < 4; ++j) bsum[j] = b1[ng + j] + b2[ng + j];
#pragma unroll
    for (int i = 0; i < 8; ++i) {
        int m = m0 + ty * 8 + i;
        float4 o;
        o.x = acc[i][0] + bsum[0]; o.y = acc[i][1] + bsum[1];
        o.z = acc[i][2] + bsum[2]; o.w = acc[i][3] + bsum[3];
        *(float4*)(C + (size_t)m * 2048 + coloff + ng) = o;
    }
}

// Persistent bi-LSTM layer: 128 CTAs (64/dir), 256 thr; CTA owns 4 h-dims.
// Gx double-buffered (prefetch t+1 during step t); float2 k-split dot.
#define LSTM_SMEM_FLOATS (4128 + 16384 + 2048 + 1040 + 256)

__global__ void lstm_kernel(int layer,
                            const float* __restrict__ whh_f,
                            const float* __restrict__ whh_b) {
    extern __shared__ float smf[];
    float* Wsl = smf;            // [16][258]
    float* Hs  = smf + 4128;     // [64][256]
    float* Gx  = Hs + 16384;     // [2][16][64]
    float* Gs  = Gx + 2048;      // [16][65]
    float* Cs  = Gs + 1040;      // [64][4]

    const float* gx   = layer ? g_gx1 : g_gx0;
    float*       hout = layer ? g_h2  : g_h1;

    const int tid = threadIdx.x;
    const int dir = blockIdx.x >> 6;
    const int j0  = (blockIdx.x & 63) * 4;
    const unsigned nct = gridDim.x;
    const float* whh = dir ? whh_b : whh_f;

    {   // weight slice: row r=grp*4+jj -> w_hh[grp*256 + j0+jj][:]
        int r = tid >> 4, k0 = (tid & 15) * 16;
        int grp = r >> 2, jj = r & 3;
        const float* src = whh + (size_t)((grp << 8) + j0 + jj) * 256 + k0;
        float* dst = Wsl + r * 258 + k0;
#pragma unroll
        for (int i = 0; i < 16; ++i) dst[i] = src[i];
    }
    const int gb = tid >> 2, gjj = tid & 3;     // gx/update mapping
    Cs[(gb << 2) + gjj] = 0.0f;
    g_hbuf[0][dir][(gb << 8) + j0 + gjj] = 0.0f;

    {   // prefill Gx[0] for t=0
        int s0 = dir ? 511 : 0;
        const float* gp = gx + ((size_t)((s0 << 6) + gb) << 11) + (dir << 10) + ((tid & 3) << 8) + j0;
        float4 v = *(const float4*)gp;
        float* gxd = Gx + (((tid & 3) << 2) << 6) + gb;
        gxd[0] = v.x; gxd[64] = v.y; gxd[128] = v.z; gxd[192] = v.w;
    }
    unsigned ph = 0;
    gbar(&ph, nct);

    const int kid  = tid & 7;
    const int tile = tid >> 3;
    const int r0 = (tile & 3) * 4;
    const int b0 = (tile >> 2) * 8;

    for (int t = 0; t < 512; ++t) {
        const int s = dir ? (511 - t) : t;
        const int cur = t & 1, nxt = cur ^ 1;

        // h(t): batch 16 independent LDGs into regs, then STS
        float4 hreg[16];
        {
            const float4* hold = (const float4*)g_hbuf[t & 1][dir];
#pragma unroll
            for (int i = 0; i < 16; ++i) hreg[i] = __ldcg(hold + (i << 8) + tid);
        }
        // prefetch gx(t+1) (independent of barrier)
        float4 gv;
        {
            int t2 = (t < 511) ? (t + 1) : t;
            int s2 = dir ? (511 - t2) : t2;
            const float* gp = gx + ((size_t)((s2 << 6) + gb) << 11) + (dir << 10) + ((tid & 3) << 8) + j0;
            gv = *(const float4*)gp;
        }
        {
            float4* hsv = (float4*)Hs;
#pragma unroll
            for (int i = 0; i < 16; ++i) hsv[(i << 8) + tid] = hreg[i];
        }
        {
            float* gxd = Gx + (nxt << 10) + (((tid & 3) << 2) << 6) + gb;
            gxd[0] = gv.x; gxd[64] = gv.y; gxd[128] = gv.z; gxd[192] = gv.w;
        }
        __syncthreads();

        // dot: acc[4 rows][8 batches], kid handles k pairs {16kk+2kid, +1}
        float acc[4][8];
#pragma unroll
        for (int i = 0; i < 4; ++i)
#pragma unroll
            for (int j = 0; j < 8; ++j) acc[i][j] = 0.0f;

        const float2* wp = (const float2*)Wsl;
        const float2* hp = (const float2*)Hs;
        const int wbase = r0 * 129 + kid;
        const int hbase = (b0 << 7) + kid;
#pragma unroll 4
        for (int kk = 0; kk < 16; ++kk) {
            const int ko = kk << 3;
            float2 w0 = wp[wbase + ko];
            float2 w1 = wp[wbase + 129 + ko];
            float2 w2 = wp[wbase + 258 + ko];
            float2 w3 = wp[wbase + 387 + ko];
#pragma unroll
            for (int j = 0; j < 8; ++j) {
                float2 hv = hp[hbase + (j << 7) + ko];
                acc[0][j] = fmaf(w0.x, hv.x, fmaf(w0.y, hv.y, acc[0][j]));
                acc[1][j] = fmaf(w1.x, hv.x, fmaf(w1.y, hv.y, acc[1][j]));
                acc[2][j] = fmaf(w2.x, hv.x, fmaf(w2.y, hv.y, acc[2][j]));
                acc[3][j] = fmaf(w3.x, hv.x, fmaf(w3.y, hv.y, acc[3][j]));
            }
        }
#pragma unroll
        for (int i = 0; i < 4; ++i)
#pragma unroll
            for (int j = 0; j < 8; ++j) {
                float v = acc[i][j];
                v += __shfl_xor_sync(0xffffffffu, v, 1);
                v += __shfl_xor_sync(0xffffffffu, v, 2);
                v += __shfl_xor_sync(0xffffffffu, v, 4);
                if (kid == 0)
                    Gs[(r0 + i) * 65 + b0 + j] = v + Gx[(cur << 10) + ((r0 + i) << 6) + b0 + j];
            }
        __syncthreads();

        {
            float gi = Gs[gjj * 65 + gb];
            float gf = Gs[(4 + gjj) * 65 + gb];
            float gg = Gs[(8 + gjj) * 65 + gb];
            float go = Gs[(12 + gjj) * 65 + gb];
            float c = sigm(gf) * Cs[(gb << 2) + gjj] + sigm(gi) * tanhf(gg);
            Cs[(gb << 2) + gjj] = c;
            float h = sigm(go) * tanhf(c);
            g_hbuf[(t + 1) & 1][dir][(gb << 8) + j0 + gjj] = h;
            hout[((size_t)((s << 6) + gb) << 9) + (dir << 8) + j0 + gjj] = h;
        }
        gbar(&ph, nct);
    }
}

__global__ void score_kernel(const float* __restrict__ wlin,
                             const float* __restrict__ blin,
                             const float* __restrict__ labels,
                             const int* __restrict__ masks,
                             float* __restrict__ outs) {
    int w = blockIdx.x * 8 + (threadIdx.x >> 5);
    int lane = threadIdx.x & 31;
    int s = w >> 6, b = w & 63;
    const float* hp = g_h2 + (size_t)w * 512;
    float acc = 0.0f;
#pragma unroll
    for (int j = lane; j < 256; j += 32)
        acc += 0.5f * (hp[j] + hp[256 + j]) * wlin[j];
#pragma unroll
    for (int d = 16; d; d >>= 1) acc += __shfl_xor_sync(0xffffffffu, acc, d);
    if (lane == 0) {
        float sc = sigm(acc + blin[0]);
        int oi = b * S_ + s;
        outs[oi] = sc;
        float df = sc - labels[oi];
        g_err[oi] = df * df * (float)masks[oi];
    }
}

__global__ void loss_kernel(const int* __restrict__ masks,
                            float* __restrict__ out, int out_size) {
    __shared__ float sr[64];
    int b = threadIdx.x;
    if (b < 64) {
        float se = 0.0f, sm = 0.0f;
        for (int s = 0; s < S_; ++s) {
            se += g_err[b * S_ + s];
            sm += (float)masks[b * S_ + s];
        }
        sr[b] = se / sm;
    }
    __syncthreads();
    if (threadIdx.x == 0 && out_size > M_) {
        float t = 0.0f;
        for (int i = 0; i < 64; ++i) t += sr[i];
        out[M_] = t / 64.0f;
    }
}

extern "C" void kernel_launch(void* const* d_in, const int* in_sizes, int n_in,
                              void* d_out, int out_size) {
    const int*   ids    = (const int*)d_in[0];
    const float* labels = (const float*)d_in[1];
    const int*   masks  = (const int*)d_in[2];
    const float* emb    = (const float*)d_in[3];
    const float* wih0f = (const float*)d_in[4];
    const float* whh0f = (const float*)d_in[5];
    const float* bih0f = (const float*)d_in[6];
    const float* bhh0f = (const float*)d_in[7];
    const float* wih0b = (const float*)d_in[8];
    const float* whh0b = (const float*)d_in[9];
    const float* bih0b = (const float*)d_in[10];
    const float* bhh0b = (const float*)d_in[11];
    const float* wih1f = (const float*)d_in[12];
    const float* whh1f = (const float*)d_in[13];
    const float* bih1f = (const float*)d_in[14];
    const float* bhh1f = (const float*)d_in[15];
    const float* wih1b = (const float*)d_in[16];
    const float* whh1b = (const float*)d_in[17];
    const float* bih1b = (const float*)d_in[18];
    const float* bhh1b = (const float*)d_in[19];
    const float* wlin  = (const float*)d_in[20];
    const float* blin  = (const float*)d_in[21];
    float* out = (float*)d_out;

    static bool attr_done = false;
    if (!attr_done) {
        cudaFuncSetAttribute(lstm_kernel, cudaFuncAttributeMaxDynamicSharedMemorySize,
                             LSTM_SMEM_FLOATS * 4);
        attr_done = true;
    }

    gather_kernel<<<M_, 128>>>(ids, emb);
    padw_kernel<<<2048, 128>>>(wih0f, wih0b);

    dim3 gg(16, 256);
    sgemm_kernel<<<gg, 256>>>(0, 0, nullptr, bih0f, bhh0f);
    sgemm_kernel<<<gg, 256>>>(0, 1, nullptr, bih0b, bhh0b);

    reset_kernel<<<1, 1>>>();
    lstm_kernel<<<128, 256, LSTM_SMEM_FLOATS * 4>>>(0, whh0f, whh0b);

    sgemm_kernel<<<gg, 256>>>(1, 0, wih1f, bih1f, bhh1f);
    sgemm_kernel<<<gg, 256>>>(1, 1, wih1b, bih1b, bhh1b);

    reset_kernel<<<1, 1>>>();
    lstm_kernel<<<128, 256, LSTM_SMEM_FLOATS * 4>>>(1, whh1f, whh1b);

    score_kernel<<<M_ / 8, 256>>>(wlin, blin, labels, masks, out);
    loss_kernel<<<1, 64>>>(masks, out, out_size);
}